// round 14
// baseline (speedup 1.0000x reference)
#include <cuda_runtime.h>
#include <cuda_fp16.h>
#include <cstdint>
#include <cstring>

#define NN 100000
#define NE 1600000
#define EB 6250            // edge blocks: 1600000/256
#define LB 1563            // lin0 blocks: ceil(100000/64)
#define PB 782             // proj blocks per half: ceil(100000/128)
#define NB 391             // node blocks: ceil(100000/256)

// ---------------- device scratch (no allocation APIs allowed) ----------------
__device__ __align__(16) float g_X[NN * 64];     // node features fp32 (post-relu)
__device__ __align__(16) uint4 g_Dpk4[NN * 16];  // dst proj fp16: lane j -> ch 4j..4j+3 {fA,fB,sA,sB}
__device__ __align__(16) uint4 g_Spk4[NN * 16];  // src proj fp16, same layout
__device__ __align__(16) unsigned g_E32[NE * 8]; // slot: {e0,e1,e2,e3 | e4,src,0,0} dup-half2
__device__ int g_deg[NN];                        // statically zero; hist fills, scatter drains
__device__ int g_off[NN + 1];                    // CSR offsets (by dst)
__device__ int g_nodeord[NN];                    // nodes sorted by degree (bucketed)
__device__ int g_bcur[64];                       // bucket cursors (rewritten each call)
__device__ unsigned g_Wf2[2 * 5 * 32];           // prepacked half2 gate weights [conv][k][pair]
__device__ unsigned g_Ws2[2 * 5 * 32];           // prepacked half2 soft weights

__device__ __forceinline__ __half2 u2h(unsigned u) {
    __half2 h;
    memcpy(&h, &u, 4);
    return h;
}
__device__ __forceinline__ unsigned h2u(__half2 h) {
    unsigned u;
    memcpy(&u, &h, 4);
    return u;
}
__device__ __forceinline__ __half2 tanh_h2(__half2 x) {
    unsigned r, xu = h2u(x);
    asm("tanh.approx.f16x2 %0, %1;" : "=r"(r) : "r"(xu));
    return u2h(r);
}
__device__ __forceinline__ __half2 ex2_h2(__half2 x) {
    unsigned r, xu = h2u(x);
    asm("ex2.approx.f16x2 %0, %1;" : "=r"(r) : "r"(xu));
    return u2h(r);
}

// ---------------------------------------------------------------------------
// Launch 1 (fused): blocks [0,EB) -> degree histogram;
// blocks [EB,EB+LB) -> X = relu(h @ lin0_w + b) (64x64 GEMM tile).
// ---------------------------------------------------------------------------
__global__ __launch_bounds__(256) void k_hist_lin0(const int* __restrict__ ei,
                                                   const float* __restrict__ h,
                                                   const float* __restrict__ w,
                                                   const float* __restrict__ b) {
    __shared__ float Xs[64 * 65];
    __shared__ float Wsm[64 * 64];
    const int t = threadIdx.x;

    if (blockIdx.x < EB) {
        int e = blockIdx.x * 256 + t;
        if (e < NE) atomicAdd(&g_deg[ei[NE + e]], 1);
        return;
    }

    const int tx = t & 15, ty = t >> 4;
    const int base = (blockIdx.x - EB) * 64;

    float acc[4][4];
#pragma unroll
    for (int i = 0; i < 4; i++)
#pragma unroll
        for (int j = 0; j < 4; j++) acc[i][j] = 0.0f;

#pragma unroll
    for (int r = 0; r < 16; r++) {
        int idx = t + 256 * r;
        int n = idx >> 6;
        int k = idx & 63;
        int gn = base + n;
        Xs[k * 65 + n] = (gn < NN) ? h[(size_t)gn * 64 + k] : 0.0f;
    }
#pragma unroll
    for (int r = 0; r < 16; r++) {
        int idx = t + 256 * r;
        Wsm[idx] = w[idx];
    }
    __syncthreads();

#pragma unroll
    for (int k = 0; k < 64; k++) {
        float xr[4], wr[4];
#pragma unroll
        for (int i = 0; i < 4; i++) xr[i] = Xs[k * 65 + i * 16 + ty];
#pragma unroll
        for (int j = 0; j < 4; j++) wr[j] = Wsm[k * 64 + j * 16 + tx];
#pragma unroll
        for (int i = 0; i < 4; i++)
#pragma unroll
            for (int j = 0; j < 4; j++)
                acc[i][j] = fmaf(xr[i], wr[j], acc[i][j]);
    }

#pragma unroll
    for (int i = 0; i < 4; i++) {
        int n = base + i * 16 + ty;
        if (n >= NN) continue;
#pragma unroll
        for (int j = 0; j < 4; j++) {
            int c = j * 16 + tx;
            g_X[(size_t)n * 64 + c] = fmaxf(acc[i][j] + b[c], 0.0f);
        }
    }
}

// ---------------------------------------------------------------------------
// Launch 2: block 0 -> exclusive scan of degrees + degree-bucket cursors;
// blocks 1,2 -> pre-pack conv weights (e-part) to half2.
// ---------------------------------------------------------------------------
__global__ __launch_bounds__(1024) void k_scan(const float* __restrict__ cfw,
                                               const float* __restrict__ csw) {
    if (blockIdx.x > 0) {
        int conv = blockIdx.x - 1;
        int t = threadIdx.x;
        if (t < 160) {
            int k = t >> 5, l = t & 31;
            const float* wef = cfw + (size_t)conv * 133 * 64 + 128 * 64;
            const float* wes = csw + (size_t)conv * 133 * 64 + 128 * 64;
            g_Wf2[conv * 160 + k * 32 + l] =
                h2u(__floats2half2_rn(wef[k * 64 + 2 * l], wef[k * 64 + 2 * l + 1]));
            g_Ws2[conv * 160 + k * 32 + l] =
                h2u(__floats2half2_rn(wes[k * 64 + 2 * l], wes[k * 64 + 2 * l + 1]));
        }
        return;
    }

    const int C = 98;
    int t = threadIdx.x;
    int beg = t * C;
    int end = min(beg + C, NN);
    int sum = 0;
    for (int i = beg; i < end; i++) sum += g_deg[i];

    __shared__ int wsum[32];
    __shared__ int cnt[64];
    if (t < 64) cnt[t] = 0;
    int lane = t & 31, wid = t >> 5;
    int v = sum;
#pragma unroll
    for (int o = 1; o < 32; o <<= 1) {
        int u = __shfl_up_sync(0xffffffffu, v, o);
        if (lane >= o) v += u;
    }
    if (lane == 31) wsum[wid] = v;
    __syncthreads();
    if (wid == 0) {
        int w = wsum[lane];
#pragma unroll
        for (int o = 1; o < 32; o <<= 1) {
            int u = __shfl_up_sync(0xffffffffu, w, o);
            if (lane >= o) w += u;
        }
        wsum[lane] = w;
    }
    __syncthreads();
    int excl = v - sum + (wid > 0 ? wsum[wid - 1] : 0);
    int run = excl;
    for (int i = beg; i < end; i++) {
        g_off[i] = run;
        int d = g_deg[i];
        run += d;
        atomicAdd(&cnt[min(d, 63)], 1);
    }
    if (t == 1023) g_off[NN] = run;
    __syncthreads();
    if (t == 0) {
        int acc2 = 0;
        for (int b2 = 0; b2 < 64; b2++) {
            g_bcur[b2] = acc2;
            acc2 += cnt[b2];
        }
    }
}

// ---------------------------------------------------------------------------
// Proj body: 128x128 tile, 8x8/thread. H=0 -> D fp16 (bias folded); H=1 -> S.
// Output layout per node: 16 uint4; lane j holds ch 4j..4j+3 as {fA,fB,sA,sB}.
// half index for packed channel c (0..127): cc=c%64; (cc>>2)*8 + (c<64?0:4) + (cc&3)
// ---------------------------------------------------------------------------
__device__ __forceinline__ void proj_body(float* Xs, float* Wsm, int bidx,
                                          const float* __restrict__ wf,
                                          const float* __restrict__ ws,
                                          const float* __restrict__ bf,
                                          const float* __restrict__ bs) {
    const int t = threadIdx.x;
    const int tx = t & 15, ty = t >> 4;
    const int H = bidx / PB;
    const int base = (bidx % PB) * 128;

    float acc[8][8];
#pragma unroll
    for (int i = 0; i < 8; i++)
#pragma unroll
        for (int j = 0; j < 8; j++) acc[i][j] = 0.0f;

    for (int ks = 0; ks < 64; ks += 32) {
        __syncthreads();
#pragma unroll
        for (int r = 0; r < 16; r++) {
            int idx = t + 256 * r;
            int n = idx >> 5;
            int k = idx & 31;
            int gn = base + n;
            Xs[k * 129 + n] = (gn < NN) ? g_X[(size_t)gn * 64 + ks + k] : 0.0f;
        }
#pragma unroll
        for (int r = 0; r < 16; r++) {
            int idx = t + 256 * r;
            int k = idx >> 7;
            int c = idx & 127;
            int grow = H * 64 + ks + k;
            Wsm[k * 128 + c] = (c < 64) ? wf[grow * 64 + c] : ws[grow * 64 + (c - 64)];
        }
        __syncthreads();
#pragma unroll
        for (int k = 0; k < 32; k++) {
            float xr[8], wr[8];
#pragma unroll
            for (int i = 0; i < 8; i++) xr[i] = Xs[k * 129 + i * 16 + ty];
#pragma unroll
            for (int j = 0; j < 8; j++) wr[j] = Wsm[k * 128 + j * 16 + tx];
#pragma unroll
            for (int i = 0; i < 8; i++)
#pragma unroll
                for (int j = 0; j < 8; j++)
                    acc[i][j] = fmaf(xr[i], wr[j], acc[i][j]);
        }
    }

    __half* outp = reinterpret_cast<__half*>(H == 0 ? g_Dpk4 : g_Spk4);
#pragma unroll
    for (int i = 0; i < 8; i++) {
        int n = base + i * 16 + ty;
        if (n >= NN) continue;
#pragma unroll
        for (int j = 0; j < 8; j++) {
            int c = j * 16 + tx;
            float v = acc[i][j];
            if (H == 0) v += (c < 64) ? bf[c] : bs[c - 64];
            int cc = (c < 64) ? c : c - 64;
            int posh = (cc >> 2) * 8 + ((c < 64) ? 0 : 4) + (cc & 3);
            outp[(size_t)n * 128 + posh] = __float2half(v);
        }
    }
}

// ---------------------------------------------------------------------------
// scatter_feat body: edge e -> slot pos; writes {5 feats dup-h2, src} as TWO
// 16B sector stores. Drains g_deg back to 0.
// ---------------------------------------------------------------------------
__device__ __forceinline__ void scatter_feat_body(int e,
                                                  const int* __restrict__ ei,
                                                  const float* __restrict__ ea,
                                                  const float* __restrict__ sw,
                                                  const float* __restrict__ sb) {
    if (e >= NE) return;
    int d = ei[NE + e];
    int old = atomicSub(&g_deg[d], 1);
    int pos = g_off[d] + old - 1;

    const float* ap = ea + (size_t)e * 5;
    float a0 = ap[0], a1 = ap[1], a2 = ap[2], a3 = ap[3], a4 = ap[4];
    unsigned r[5];
#pragma unroll
    for (int c = 0; c < 5; c++) {
        float acc = sb[c];
        acc = fmaf(a0, sw[0 * 5 + c], acc);
        acc = fmaf(a1, sw[1 * 5 + c], acc);
        acc = fmaf(a2, sw[2 * 5 + c], acc);
        acc = fmaf(a3, sw[3 * 5 + c], acc);
        acc = fmaf(a4, sw[4 * 5 + c], acc);
        r[c] = h2u(__float2half2_rn(fmaxf(acc, 0.0f)));
    }
    uint4* o0 = reinterpret_cast<uint4*>(&g_E32[(size_t)pos * 8]);
    o0[0] = make_uint4(r[0], r[1], r[2], r[3]);
    o0[1] = make_uint4(r[4], (unsigned)ei[e], 0u, 0u);
}

// ---------------------------------------------------------------------------
// Launch 3 (fused): [0,2PB) proj conv#1; [2PB,2PB+EB) scatter_feat;
// [2PB+EB,..) degree-bucket node scatter -> g_nodeord (counting sort).
// ---------------------------------------------------------------------------
__global__ __launch_bounds__(256) void k_scat_proj(const int* __restrict__ ei,
                                                   const float* __restrict__ ea,
                                                   const float* __restrict__ sw,
                                                   const float* __restrict__ sb,
                                                   const float* __restrict__ wf,
                                                   const float* __restrict__ ws,
                                                   const float* __restrict__ bf,
                                                   const float* __restrict__ bs) {
    __shared__ float Xs[32 * 129];
    __shared__ float Wsm[32 * 128];
    if (blockIdx.x < 2 * PB) {
        proj_body(Xs, Wsm, blockIdx.x, wf, ws, bf, bs);
    } else if (blockIdx.x < 2 * PB + EB) {
        int e = (blockIdx.x - 2 * PB) * 256 + threadIdx.x;
        scatter_feat_body(e, ei, ea, sw, sb);
    } else {
        int n = (blockIdx.x - 2 * PB - EB) * 256 + threadIdx.x;
        if (n < NN) {
            int d = g_off[n + 1] - g_off[n];
            int pos = atomicAdd(&g_bcur[min(d, 63)], 1);
            g_nodeord[pos] = n;
        }
    }
}

__global__ __launch_bounds__(256) void k_proj(const float* __restrict__ wf,
                                              const float* __restrict__ ws,
                                              const float* __restrict__ bf,
                                              const float* __restrict__ bs) {
    __shared__ float Xs[32 * 129];
    __shared__ float Wsm[32 * 128];
    proj_body(Xs, Wsm, blockIdx.x, wf, ws, bf, bs);
}

// ---------------------------------------------------------------------------
// K_edge_csr: one WARP per dst node (degree-sorted order). Half-warp le owns
// one edge of a pair; lane group lc (=l&15) owns channels 4lc..4lc+3 as two
// half2 regs. Per 2 edges: 2 E-slot LDG.128 + 1 S LDG.128. softplus front-end
// in f16x2 (ex2.approx), lg2 in f32. Half-warps combine via shfl_xor(16).
// Fused residual + relu epilogue.
// ---------------------------------------------------------------------------
__global__ __launch_bounds__(256) void k_edge_csr(const unsigned* __restrict__ wfp,
                                                  const unsigned* __restrict__ wsp,
                                                  float* __restrict__ out,
                                                  int final_) {
    int gw = (blockIdx.x * 256 + threadIdx.x) >> 5;
    int l = threadIdx.x & 31;
    if (gw >= NN) return;
    const int n = g_nodeord[gw];
    const int le = l >> 4;   // which edge of the pair
    const int lc = l & 15;   // channel group: 4lc..4lc+3

    __half2 wfA[5], wfB[5], wsA[5], wsB[5];
#pragma unroll
    for (int k = 0; k < 5; k++) {
        wfA[k] = u2h(wfp[k * 32 + 2 * lc]);
        wfB[k] = u2h(wfp[k * 32 + 2 * lc + 1]);
        wsA[k] = u2h(wsp[k * 32 + 2 * lc]);
        wsB[k] = u2h(wsp[k * 32 + 2 * lc + 1]);
    }
    const __half2 cHalf = __float2half2_rn(0.5f);
    const __half2 cOne = __float2half2_rn(1.0f);
    const __half2 nl2e = __float2half2_rn(-1.4426950408889634f);

    uint4 dw = g_Dpk4[(size_t)n * 16 + lc];
    const __half2 DfA = u2h(dw.x), DfB = u2h(dw.y);
    const __half2 DsA = u2h(dw.z), DsB = u2h(dw.w);

    float m0 = 0.0f, m1 = 0.0f, m2 = 0.0f, m3 = 0.0f;
    const int beg = __ldg(&g_off[n]), end = __ldg(&g_off[n + 1]);

#pragma unroll 2
    for (int k = beg + le; k < end; k += 2) {
        uint4 ewa = *reinterpret_cast<const uint4*>(&g_E32[(size_t)k * 8]);
        uint4 ewb = *reinterpret_cast<const uint4*>(&g_E32[(size_t)k * 8 + 4]);
        int s = (int)ewb.y;
        uint4 sp = __ldg(&g_Spk4[(size_t)s * 16 + lc]);

        __half2 e0 = u2h(ewa.x), e1 = u2h(ewa.y), e2 = u2h(ewa.z),
                e3 = u2h(ewa.w), e4 = u2h(ewb.x);

        __half2 zfA = __hadd2(DfA, u2h(sp.x));
        zfA = __hfma2(e0, wfA[0], zfA);
        zfA = __hfma2(e1, wfA[1], zfA);
        zfA = __hfma2(e2, wfA[2], zfA);
        zfA = __hfma2(e3, wfA[3], zfA);
        zfA = __hfma2(e4, wfA[4], zfA);
        __half2 zfB = __hadd2(DfB, u2h(sp.y));
        zfB = __hfma2(e0, wfB[0], zfB);
        zfB = __hfma2(e1, wfB[1], zfB);
        zfB = __hfma2(e2, wfB[2], zfB);
        zfB = __hfma2(e3, wfB[3], zfB);
        zfB = __hfma2(e4, wfB[4], zfB);
        __half2 zsA = __hadd2(DsA, u2h(sp.z));
        zsA = __hfma2(e0, wsA[0], zsA);
        zsA = __hfma2(e1, wsA[1], zsA);
        zsA = __hfma2(e2, wsA[2], zsA);
        zsA = __hfma2(e3, wsA[3], zsA);
        zsA = __hfma2(e4, wsA[4], zsA);
        __half2 zsB = __hadd2(DsB, u2h(sp.w));
        zsB = __hfma2(e0, wsB[0], zsB);
        zsB = __hfma2(e1, wsB[1], zsB);
        zsB = __hfma2(e2, wsB[2], zsB);
        zsB = __hfma2(e3, wsB[3], zsB);
        zsB = __hfma2(e4, wsB[4], zsB);

        // gate = sigmoid(zf)
        __half2 gA = __hfma2(tanh_h2(__hmul2(zfA, cHalf)), cHalf, cHalf);
        __half2 gB = __hfma2(tanh_h2(__hmul2(zfB, cHalf)), cHalf, cHalf);

        // softplus(zs) = max(zs,0) + ln2*log2(1 + 2^(-|zs|*log2e))
        __half2 uA = ex2_h2(__hmul2(__habs2(zsA), nl2e));
        __half2 uB = ex2_h2(__hmul2(__habs2(zsB), nl2e));
        float2 va = __half22float2(__hadd2(uA, cOne));
        float2 vb = __half22float2(__hadd2(uB, cOne));
        float2 za = __half22float2(zsA);
        float2 zb = __half22float2(zsB);
        float2 ga = __half22float2(gA);
        float2 gb = __half22float2(gB);

        const float LN2 = 0.6931471805599453f;
        float sp0 = fmaf(__log2f(va.x), LN2, fmaxf(za.x, 0.0f));
        float sp1 = fmaf(__log2f(va.y), LN2, fmaxf(za.y, 0.0f));
        float sp2 = fmaf(__log2f(vb.x), LN2, fmaxf(zb.x, 0.0f));
        float sp3 = fmaf(__log2f(vb.y), LN2, fmaxf(zb.y, 0.0f));

        m0 = fmaf(ga.x, sp0, m0);
        m1 = fmaf(ga.y, sp1, m1);
        m2 = fmaf(gb.x, sp2, m2);
        m3 = fmaf(gb.y, sp3, m3);
    }

    // combine the two half-warps' partial sums (channels identical across halves)
    m0 += __shfl_xor_sync(0xffffffffu, m0, 16);
    m1 += __shfl_xor_sync(0xffffffffu, m1, 16);
    m2 += __shfl_xor_sync(0xffffffffu, m2, 16);
    m3 += __shfl_xor_sync(0xffffffffu, m3, 16);

    if (le == 0) {
        float4 x = *reinterpret_cast<const float4*>(g_X + (size_t)n * 64 + 4 * lc);
        float4 r;
        r.x = fmaxf(x.x + m0, 0.0f);
        r.y = fmaxf(x.y + m1, 0.0f);
        r.z = fmaxf(x.z + m2, 0.0f);
        r.w = fmaxf(x.w + m3, 0.0f);
        if (final_) {
            *reinterpret_cast<float4*>(out + (size_t)n * 64 + 4 * lc) = r;
        } else {
            *reinterpret_cast<float4*>(g_X + (size_t)n * 64 + 4 * lc) = r;
        }
    }
}

// ---------------------------------------------------------------------------
// Launch. Inputs: h, edge_index, edge_weight, edge_attr, data,
// lin0_w, lin0_b, short_w, short_b, conv_f_w, conv_f_b, conv_s_w, conv_s_b
// 6 launches; launch 4 = edge conv #1 (observed ncu target).
// ---------------------------------------------------------------------------
extern "C" void kernel_launch(void* const* d_in, const int* in_sizes, int n_in,
                              void* d_out, int out_size) {
    int o = (n_in >= 13) ? 0 : -1;

    const float* h = (const float*)d_in[0];
    const int* ei = (const int*)d_in[1];  // int32 [2, NE]
    const float* ea = (const float*)d_in[3];
    const float* lin0_w = (const float*)d_in[5 + o];
    const float* lin0_b = (const float*)d_in[6 + o];
    const float* short_w = (const float*)d_in[7 + o];
    const float* short_b = (const float*)d_in[8 + o];
    const float* cfw = (const float*)d_in[9 + o];   // [2,133,64]
    const float* cfb = (const float*)d_in[10 + o];  // [2,64]
    const float* csw = (const float*)d_in[11 + o];
    const float* csb = (const float*)d_in[12 + o];
    float* out = (float*)d_out;

    unsigned* wf2dev = nullptr;
    unsigned* ws2dev = nullptr;
    cudaGetSymbolAddress((void**)&wf2dev, g_Wf2);
    cudaGetSymbolAddress((void**)&ws2dev, g_Ws2);

    // 1: histogram + lin0
    k_hist_lin0<<<EB + LB, 256>>>(ei, h, lin0_w, lin0_b);
    // 2: offsets + degree buckets + weight prepack
    k_scan<<<3, 1024>>>(cfw, csw);
    // 3: proj conv#1 + scatter_feat + node counting-sort
    k_scat_proj<<<2 * PB + EB + NB, 256>>>(ei, ea, short_w, short_b,
                                           cfw, csw, cfb, csb);
    // 4: edge conv #1
    k_edge_csr<<<(NN * 32 + 255) / 256, 256>>>(wf2dev, ws2dev, out, 0);
    // 5: proj conv #2
    k_proj<<<2 * PB, 256>>>(cfw + (size_t)133 * 64, csw + (size_t)133 * 64,
                            cfb + 64, csb + 64);
    // 6: edge conv #2
    k_edge_csr<<<(NN * 32 + 255) / 256, 256>>>(wf2dev + 160, ws2dev + 160, out, 1);
}

// round 15
// speedup vs baseline: 1.0451x; 1.0451x over previous
#include <cuda_runtime.h>
#include <cuda_fp16.h>
#include <cstdint>
#include <cstring>

#define NN 100000
#define NE 1600000
#define EB 6250            // edge blocks: 1600000/256
#define LB 1563            // lin0 blocks: ceil(100000/64)
#define PB 782             // proj blocks per half: ceil(100000/128)
#define NB 391             // node blocks: ceil(100000/256)

// ---------------- device scratch (no allocation APIs allowed) ----------------
__device__ __align__(16) float g_X[NN * 64];     // node features fp32 (post-relu)
__device__ __align__(16) uint2 g_Dpk[NN * 32];   // dst proj packed fp16 (bias folded)
__device__ __align__(16) uint2 g_Spk[NN * 32];   // src proj packed fp16
__device__ __align__(16) unsigned g_E32[NE * 8]; // slot: {e0,e1,e2,e3 | e4,src,0,0}
__device__ int g_deg[NN];                        // statically zero; hist fills, scatter drains
__device__ int g_off[NN + 1];                    // CSR offsets (by dst)
__device__ int g_nodeord[NN];                    // nodes sorted by degree DESC (bucketed)
__device__ int g_bcur[64];                       // bucket cursors (rewritten each call)
__device__ unsigned g_Wf2[2 * 5 * 32];           // prepacked half2 gate weights [conv][k][lane]
__device__ unsigned g_Ws2[2 * 5 * 32];           // prepacked half2 soft weights

__device__ __forceinline__ __half2 u2h(unsigned u) {
    __half2 h;
    memcpy(&h, &u, 4);
    return h;
}
__device__ __forceinline__ unsigned h2u(__half2 h) {
    unsigned u;
    memcpy(&u, &h, 4);
    return u;
}
__device__ __forceinline__ __half2 tanh_h2(__half2 x) {
    unsigned r, xu = h2u(x);
    asm("tanh.approx.f16x2 %0, %1;" : "=r"(r) : "r"(xu));
    return u2h(r);
}
__device__ __forceinline__ __half2 ex2_h2(__half2 x) {
    unsigned r, xu = h2u(x);
    asm("ex2.approx.f16x2 %0, %1;" : "=r"(r) : "r"(xu));
    return u2h(r);
}

// ---------------------------------------------------------------------------
// Launch 1 (fused): blocks [0,EB) -> degree histogram;
// blocks [EB,EB+LB) -> X = relu(h @ lin0_w + b) (64x64 GEMM tile).
// ---------------------------------------------------------------------------
__global__ __launch_bounds__(256) void k_hist_lin0(const int* __restrict__ ei,
                                                   const float* __restrict__ h,
                                                   const float* __restrict__ w,
                                                   const float* __restrict__ b) {
    __shared__ float Xs[64 * 65];
    __shared__ float Wsm[64 * 64];
    const int t = threadIdx.x;

    if (blockIdx.x < EB) {
        int e = blockIdx.x * 256 + t;
        if (e < NE) atomicAdd(&g_deg[ei[NE + e]], 1);
        return;
    }

    const int tx = t & 15, ty = t >> 4;
    const int base = (blockIdx.x - EB) * 64;

    float acc[4][4];
#pragma unroll
    for (int i = 0; i < 4; i++)
#pragma unroll
        for (int j = 0; j < 4; j++) acc[i][j] = 0.0f;

#pragma unroll
    for (int r = 0; r < 16; r++) {
        int idx = t + 256 * r;
        int n = idx >> 6;
        int k = idx & 63;
        int gn = base + n;
        Xs[k * 65 + n] = (gn < NN) ? h[(size_t)gn * 64 + k] : 0.0f;
    }
#pragma unroll
    for (int r = 0; r < 16; r++) {
        int idx = t + 256 * r;
        Wsm[idx] = w[idx];
    }
    __syncthreads();

#pragma unroll
    for (int k = 0; k < 64; k++) {
        float xr[4], wr[4];
#pragma unroll
        for (int i = 0; i < 4; i++) xr[i] = Xs[k * 65 + i * 16 + ty];
#pragma unroll
        for (int j = 0; j < 4; j++) wr[j] = Wsm[k * 64 + j * 16 + tx];
#pragma unroll
        for (int i = 0; i < 4; i++)
#pragma unroll
            for (int j = 0; j < 4; j++)
                acc[i][j] = fmaf(xr[i], wr[j], acc[i][j]);
    }

#pragma unroll
    for (int i = 0; i < 4; i++) {
        int n = base + i * 16 + ty;
        if (n >= NN) continue;
#pragma unroll
        for (int j = 0; j < 4; j++) {
            int c = j * 16 + tx;
            g_X[(size_t)n * 64 + c] = fmaxf(acc[i][j] + b[c], 0.0f);
        }
    }
}

// ---------------------------------------------------------------------------
// Launch 2: block 0 -> exclusive scan of degrees + DESC-degree bucket cursors;
// blocks 1,2 -> pre-pack conv weights (e-part) to half2.
// ---------------------------------------------------------------------------
__global__ __launch_bounds__(1024) void k_scan(const float* __restrict__ cfw,
                                               const float* __restrict__ csw) {
    if (blockIdx.x > 0) {
        int conv = blockIdx.x - 1;
        int t = threadIdx.x;
        if (t < 160) {
            int k = t >> 5, l = t & 31;
            const float* wef = cfw + (size_t)conv * 133 * 64 + 128 * 64;
            const float* wes = csw + (size_t)conv * 133 * 64 + 128 * 64;
            g_Wf2[conv * 160 + k * 32 + l] =
                h2u(__floats2half2_rn(wef[k * 64 + 2 * l], wef[k * 64 + 2 * l + 1]));
            g_Ws2[conv * 160 + k * 32 + l] =
                h2u(__floats2half2_rn(wes[k * 64 + 2 * l], wes[k * 64 + 2 * l + 1]));
        }
        return;
    }

    const int C = 98;
    int t = threadIdx.x;
    int beg = t * C;
    int end = min(beg + C, NN);
    int sum = 0;
    for (int i = beg; i < end; i++) sum += g_deg[i];

    __shared__ int wsum[32];
    __shared__ int cnt[64];
    if (t < 64) cnt[t] = 0;
    int lane = t & 31, wid = t >> 5;
    int v = sum;
#pragma unroll
    for (int o = 1; o < 32; o <<= 1) {
        int u = __shfl_up_sync(0xffffffffu, v, o);
        if (lane >= o) v += u;
    }
    if (lane == 31) wsum[wid] = v;
    __syncthreads();
    if (wid == 0) {
        int w = wsum[lane];
#pragma unroll
        for (int o = 1; o < 32; o <<= 1) {
            int u = __shfl_up_sync(0xffffffffu, w, o);
            if (lane >= o) w += u;
        }
        wsum[lane] = w;
    }
    __syncthreads();
    int excl = v - sum + (wid > 0 ? wsum[wid - 1] : 0);
    int run = excl;
    for (int i = beg; i < end; i++) {
        g_off[i] = run;
        int d = g_deg[i];
        run += d;
        atomicAdd(&cnt[min(d, 63)], 1);
    }
    if (t == 1023) g_off[NN] = run;
    __syncthreads();
    if (t == 0) {
        // DESCENDING degree order: bucket 63 first -> longest CTAs launch first
        int acc2 = 0;
        for (int b2 = 63; b2 >= 0; b2--) {
            g_bcur[b2] = acc2;
            acc2 += cnt[b2];
        }
    }
}

// ---------------------------------------------------------------------------
// Proj body: 128x128 tile, 8x8/thread. H=0 -> D fp16 (bias folded); H=1 -> S.
// Packed layout: lane l holds ch 2l,2l+1 as {f-h2 | s-h2} (uint2).
// ---------------------------------------------------------------------------
__device__ __forceinline__ void proj_body(float* Xs, float* Wsm, int bidx,
                                          const float* __restrict__ wf,
                                          const float* __restrict__ ws,
                                          const float* __restrict__ bf,
                                          const float* __restrict__ bs) {
    const int t = threadIdx.x;
    const int tx = t & 15, ty = t >> 4;
    const int H = bidx / PB;
    const int base = (bidx % PB) * 128;

    float acc[8][8];
#pragma unroll
    for (int i = 0; i < 8; i++)
#pragma unroll
        for (int j = 0; j < 8; j++) acc[i][j] = 0.0f;

    for (int ks = 0; ks < 64; ks += 32) {
        __syncthreads();
#pragma unroll
        for (int r = 0; r < 16; r++) {
            int idx = t + 256 * r;
            int n = idx >> 5;
            int k = idx & 31;
            int gn = base + n;
            Xs[k * 129 + n] = (gn < NN) ? g_X[(size_t)gn * 64 + ks + k] : 0.0f;
        }
#pragma unroll
        for (int r = 0; r < 16; r++) {
            int idx = t + 256 * r;
            int k = idx >> 7;
            int c = idx & 127;
            int grow = H * 64 + ks + k;
            Wsm[k * 128 + c] = (c < 64) ? wf[grow * 64 + c] : ws[grow * 64 + (c - 64)];
        }
        __syncthreads();
#pragma unroll
        for (int k = 0; k < 32; k++) {
            float xr[8], wr[8];
#pragma unroll
            for (int i = 0; i < 8; i++) xr[i] = Xs[k * 129 + i * 16 + ty];
#pragma unroll
            for (int j = 0; j < 8; j++) wr[j] = Wsm[k * 128 + j * 16 + tx];
#pragma unroll
            for (int i = 0; i < 8; i++)
#pragma unroll
                for (int j = 0; j < 8; j++)
                    acc[i][j] = fmaf(xr[i], wr[j], acc[i][j]);
        }
    }

    __half* outp = reinterpret_cast<__half*>(H == 0 ? g_Dpk : g_Spk);
#pragma unroll
    for (int i = 0; i < 8; i++) {
        int n = base + i * 16 + ty;
        if (n >= NN) continue;
#pragma unroll
        for (int j = 0; j < 8; j++) {
            int c = j * 16 + tx;
            float v = acc[i][j];
            if (H == 0) v += (c < 64) ? bf[c] : bs[c - 64];
            int cc = (c < 64) ? c : c - 64;
            int posh = 4 * (cc >> 1) + ((c < 64) ? 0 : 2) + (cc & 1);
            outp[(size_t)n * 128 + posh] = __float2half(v);
        }
    }
}

// ---------------------------------------------------------------------------
// scatter_feat body: edge e -> slot pos; writes {5 feats dup-h2, src} as TWO
// 16B sector stores. Drains g_deg back to 0.
// ---------------------------------------------------------------------------
__device__ __forceinline__ void scatter_feat_body(int e,
                                                  const int* __restrict__ ei,
                                                  const float* __restrict__ ea,
                                                  const float* __restrict__ sw,
                                                  const float* __restrict__ sb) {
    if (e >= NE) return;
    int d = ei[NE + e];
    int old = atomicSub(&g_deg[d], 1);
    int pos = g_off[d] + old - 1;

    const float* ap = ea + (size_t)e * 5;
    float a0 = ap[0], a1 = ap[1], a2 = ap[2], a3 = ap[3], a4 = ap[4];
    unsigned r[5];
#pragma unroll
    for (int c = 0; c < 5; c++) {
        float acc = sb[c];
        acc = fmaf(a0, sw[0 * 5 + c], acc);
        acc = fmaf(a1, sw[1 * 5 + c], acc);
        acc = fmaf(a2, sw[2 * 5 + c], acc);
        acc = fmaf(a3, sw[3 * 5 + c], acc);
        acc = fmaf(a4, sw[4 * 5 + c], acc);
        r[c] = h2u(__float2half2_rn(fmaxf(acc, 0.0f)));
    }
    uint4* o0 = reinterpret_cast<uint4*>(&g_E32[(size_t)pos * 8]);
    o0[0] = make_uint4(r[0], r[1], r[2], r[3]);
    o0[1] = make_uint4(r[4], (unsigned)ei[e], 0u, 0u);
}

// ---------------------------------------------------------------------------
// Launch 3 (fused): [0,2PB) proj conv#1; [2PB,2PB+EB) scatter_feat;
// [2PB+EB,..) degree-bucket node scatter -> g_nodeord (counting sort, DESC).
// ---------------------------------------------------------------------------
__global__ __launch_bounds__(256) void k_scat_proj(const int* __restrict__ ei,
                                                   const float* __restrict__ ea,
                                                   const float* __restrict__ sw,
                                                   const float* __restrict__ sb,
                                                   const float* __restrict__ wf,
                                                   const float* __restrict__ ws,
                                                   const float* __restrict__ bf,
                                                   const float* __restrict__ bs) {
    __shared__ float Xs[32 * 129];
    __shared__ float Wsm[32 * 128];
    if (blockIdx.x < 2 * PB) {
        proj_body(Xs, Wsm, blockIdx.x, wf, ws, bf, bs);
    } else if (blockIdx.x < 2 * PB + EB) {
        int e = (blockIdx.x - 2 * PB) * 256 + threadIdx.x;
        scatter_feat_body(e, ei, ea, sw, sb);
    } else {
        int n = (blockIdx.x - 2 * PB - EB) * 256 + threadIdx.x;
        if (n < NN) {
            int d = g_off[n + 1] - g_off[n];
            int pos = atomicAdd(&g_bcur[min(d, 63)], 1);
            g_nodeord[pos] = n;
        }
    }
}

__global__ __launch_bounds__(256) void k_proj(const float* __restrict__ wf,
                                              const float* __restrict__ ws,
                                              const float* __restrict__ bf,
                                              const float* __restrict__ bs) {
    __shared__ float Xs[32 * 129];
    __shared__ float Wsm[32 * 128];
    proj_body(Xs, Wsm, blockIdx.x, wf, ws, bf, bs);
}

// ---------------------------------------------------------------------------
// K_edge_csr: one WARP per dst node, nodes in DESC-degree order. Lane l owns
// channels 2l,2l+1 as half2; weights pre-packed. Per edge: 2 broadcast
// LDG.128 + 1 LDG.64 gather. f16x2 ex2 softplus front-end; lg2 in f32.
// Unroll 4; fused residual + relu epilogue.
// ---------------------------------------------------------------------------
__global__ __launch_bounds__(256) void k_edge_csr(const unsigned* __restrict__ wfp,
                                                  const unsigned* __restrict__ wsp,
                                                  float* __restrict__ out,
                                                  int final_) {
    int gw = (blockIdx.x * 256 + threadIdx.x) >> 5;
    int l = threadIdx.x & 31;
    if (gw >= NN) return;
    const int n = g_nodeord[gw];

    __half2 wf2[5], ws2[5];
#pragma unroll
    for (int k = 0; k < 5; k++) {
        wf2[k] = u2h(wfp[k * 32 + l]);
        ws2[k] = u2h(wsp[k * 32 + l]);
    }
    const __half2 cHalf = __float2half2_rn(0.5f);
    const __half2 cOne = __float2half2_rn(1.0f);
    const __half2 nl2e = __float2half2_rn(-1.4426950408889634f);
    const float LN2 = 0.6931471805599453f;

    uint2 dw = g_Dpk[(size_t)n * 32 + l];
    const __half2 Df2 = u2h(dw.x);
    const __half2 Ds2 = u2h(dw.y);

    float m0 = 0.0f, m1 = 0.0f;
    const int beg = __ldg(&g_off[n]), end = __ldg(&g_off[n + 1]);

#pragma unroll 4
    for (int k = beg; k < end; k++) {
        uint4 ewa = *reinterpret_cast<const uint4*>(&g_E32[(size_t)k * 8]);
        uint4 ewb = *reinterpret_cast<const uint4*>(&g_E32[(size_t)k * 8 + 4]);
        int s = (int)ewb.y;                                   // src id
        uint2 sp_ = __ldg(&g_Spk[(size_t)s * 32 + l]);        // 8B gather

        __half2 zf = __hadd2(Df2, u2h(sp_.x));
        zf = __hfma2(u2h(ewa.x), wf2[0], zf);
        zf = __hfma2(u2h(ewa.y), wf2[1], zf);
        zf = __hfma2(u2h(ewa.z), wf2[2], zf);
        zf = __hfma2(u2h(ewa.w), wf2[3], zf);
        zf = __hfma2(u2h(ewb.x), wf2[4], zf);

        __half2 zs = __hadd2(Ds2, u2h(sp_.y));
        zs = __hfma2(u2h(ewa.x), ws2[0], zs);
        zs = __hfma2(u2h(ewa.y), ws2[1], zs);
        zs = __hfma2(u2h(ewa.z), ws2[2], zs);
        zs = __hfma2(u2h(ewa.w), ws2[3], zs);
        zs = __hfma2(u2h(ewb.x), ws2[4], zs);

        // gate = sigmoid(zf) via f16x2 tanh (1 MUFU for both channels)
        __half2 g2 = __hfma2(tanh_h2(__hmul2(zf, cHalf)), cHalf, cHalf);
        float2 gf = __half22float2(g2);

        // softplus(zs) = max(zs,0) + ln2*log2(1 + 2^(-|zs|*log2e));
        // ex2 in f16x2 (1 MUFU for both channels), lg2 in f32.
        __half2 uh = ex2_h2(__hmul2(__habs2(zs), nl2e));
        float2 v = __half22float2(__hadd2(uh, cOne));
        float2 zsf = __half22float2(zs);

        float sp0 = fmaf(__log2f(v.x), LN2, fmaxf(zsf.x, 0.0f));
        float sp1 = fmaf(__log2f(v.y), LN2, fmaxf(zsf.y, 0.0f));

        m0 = fmaf(gf.x, sp0, m0);
        m1 = fmaf(gf.y, sp1, m1);
    }

    float2 x = *reinterpret_cast<const float2*>(g_X + (size_t)n * 64 + 2 * l);
    float2 r = make_float2(fmaxf(x.x + m0, 0.0f), fmaxf(x.y + m1, 0.0f));
    if (final_) {
        *reinterpret_cast<float2*>(out + (size_t)n * 64 + 2 * l) = r;
    } else {
        *reinterpret_cast<float2*>(g_X + (size_t)n * 64 + 2 * l) = r;
    }
}

// ---------------------------------------------------------------------------
// Launch. Inputs: h, edge_index, edge_weight, edge_attr, data,
// lin0_w, lin0_b, short_w, short_b, conv_f_w, conv_f_b, conv_s_w, conv_s_b
// 6 launches.
// ---------------------------------------------------------------------------
extern "C" void kernel_launch(void* const* d_in, const int* in_sizes, int n_in,
                              void* d_out, int out_size) {
    int o = (n_in >= 13) ? 0 : -1;

    const float* h = (const float*)d_in[0];
    const int* ei = (const int*)d_in[1];  // int32 [2, NE]
    const float* ea = (const float*)d_in[3];
    const float* lin0_w = (const float*)d_in[5 + o];
    const float* lin0_b = (const float*)d_in[6 + o];
    const float* short_w = (const float*)d_in[7 + o];
    const float* short_b = (const float*)d_in[8 + o];
    const float* cfw = (const float*)d_in[9 + o];   // [2,133,64]
    const float* cfb = (const float*)d_in[10 + o];  // [2,64]
    const float* csw = (const float*)d_in[11 + o];
    const float* csb = (const float*)d_in[12 + o];
    float* out = (float*)d_out;

    unsigned* wf2dev = nullptr;
    unsigned* ws2dev = nullptr;
    cudaGetSymbolAddress((void**)&wf2dev, g_Wf2);
    cudaGetSymbolAddress((void**)&ws2dev, g_Ws2);

    // 1: histogram + lin0
    k_hist_lin0<<<EB + LB, 256>>>(ei, h, lin0_w, lin0_b);
    // 2: offsets + DESC degree buckets + weight prepack
    k_scan<<<3, 1024>>>(cfw, csw);
    // 3: proj conv#1 + scatter_feat + node counting-sort (DESC)
    k_scat_proj<<<2 * PB + EB + NB, 256>>>(ei, ea, short_w, short_b,
                                           cfw, csw, cfb, csb);
    // 4: edge conv #1
    k_edge_csr<<<(NN * 32 + 255) / 256, 256>>>(wf2dev, ws2dev, out, 0);
    // 5: proj conv #2
    k_proj<<<2 * PB, 256>>>(cfw + (size_t)133 * 64, csw + (size_t)133 * 64,
                            cfb + 64, csb + 64);
    // 6: edge conv #2
    k_edge_csr<<<(NN * 32 + 255) / 256, 256>>>(wf2dev + 160, ws2dev + 160, out, 1);
}